// round 1
// baseline (speedup 1.0000x reference)
#include <cuda_runtime.h>

#define B    8
#define A    49104
#define C    20
#define M    32
#define NANN 16
#define AC   (A * C)

// ---- scratch (device globals; no allocations allowed) ----
__device__ float         g_cls[B];
__device__ float         g_reg[B];
__device__ int           g_npos[B];
__device__ unsigned char g_assigned[B][A];

__global__ void k_init() {
    int t = threadIdx.x;
    if (t < B) { g_cls[t] = 0.f; g_reg[t] = 0.f; g_npos[t] = 0; }
}

// Kernel 1: per (b, anchor) IoU assignment + reg consistency loss + npos
__global__ void __launch_bounds__(256) k_assign(
    const float* __restrict__ regressions,    // [B,A,4]
    const float* __restrict__ anchors,        // [1,A,4]
    const float* __restrict__ ema_classes,    // [B,M]
    const float* __restrict__ ema_bboxes,     // [B,M,4]
    const int*   __restrict__ ema_counts,     // [B]
    const float* __restrict__ annotations)    // [B,N,5]
{
    __shared__ float sbx1[B][M], sby1[B][M], sbx2[B][M], sby2[B][M], sarea[B][M];
    __shared__ unsigned skeep[B];
    __shared__ float s_reg[B];
    __shared__ int   s_npos[B];

    int tid = threadIdx.x;
    if (tid < B) { s_reg[tid] = 0.f; s_npos[tid] = 0; }

    // 256 threads = 8 warps; warp b handles batch b's 32 ema boxes
    {
        int b = tid >> 5, m = tid & 31;
        const float* bb = ema_bboxes + (b * M + m) * 4;
        float x1 = bb[0], y1 = bb[1], x2 = bb[2], y2 = bb[3];
        sbx1[b][m] = x1; sby1[b][m] = y1; sbx2[b][m] = x2; sby2[b][m] = y2;
        sarea[b][m] = (x2 - x1) * (y2 - y1);
        bool valid = m < ema_counts[b];
        float cls = ema_classes[b * M + m];
        bool member = false;
        #pragma unroll
        for (int n = 0; n < NANN; n++)
            member |= (cls == annotations[(b * NANN + n) * 5 + 4]);
        unsigned mask = __ballot_sync(0xffffffffu, valid && member);
        if (m == 0) skeep[b] = mask;
    }
    __syncthreads();

    int a = blockIdx.x * 256 + tid;
    if (a < A) {
        float4 an = ((const float4*)anchors)[a];
        float aw = an.z - an.x, ah = an.w - an.y;
        float acx = an.x + 0.5f * aw, acy = an.y + 0.5f * ah;
        float area_a = aw * ah;

        #pragma unroll
        for (int b = 0; b < B; b++) {
            unsigned km = skeep[b];
            float best = -1.f;
            int besti = 0;
            unsigned mm = km;
            // ascending m, strict '>' => first-argmax (matches jnp.argmax);
            // masked entries (-1) can never beat a kept IoU (>= 0)
            while (mm) {
                int m = __ffs(mm) - 1;
                mm &= mm - 1;
                float iw = fminf(an.z, sbx2[b][m]) - fmaxf(an.x, sbx1[b][m]);
                float ih = fminf(an.w, sby2[b][m]) - fmaxf(an.y, sby1[b][m]);
                iw = fmaxf(iw, 0.f);
                ih = fmaxf(ih, 0.f);
                float inter = iw * ih;
                float ua = fmaxf(area_a + sarea[b][m] - inter, 1e-8f);
                float iou = inter / ua;
                if (iou > best) { best = iou; besti = m; }
            }
            bool has = (km != 0u);
            bool pos = has && (best >= 0.5f);
            bool assigned = has && ((best < 0.4f) || (best >= 0.5f));
            g_assigned[b][a] = assigned ? (unsigned char)1 : (unsigned char)0;

            if (pos) {
                atomicAdd(&s_npos[b], 1);
                const float* r = regressions + ((size_t)b * A + a) * 4;
                float r0 = r[0], r1 = r[1], r2 = r[2], r3 = r[3];
                float bx1 = sbx1[b][besti], by1 = sby1[b][besti];
                float bx2 = sbx2[b][besti], by2 = sby2[b][besti];
                float gw = bx2 - bx1, gh = by2 - by1;
                float gcx = bx1 + 0.5f * gw, gcy = by1 + 0.5f * gh;
                gw = fmaxf(gw, 1.f);
                gh = fmaxf(gh, 1.f);
                float dx = (gcx - acx) / aw / 0.1f;
                float dy = (gcy - acy) / ah / 0.1f;
                float dw = __logf(gw / aw) / 0.2f;
                float dh = __logf(gh / ah) / 0.2f;
                float s = 0.f, d;
                d = fabsf(dx - r0); s += (d <= 1.f / 9.f) ? 4.5f * d * d : d - 0.5f / 9.f;
                d = fabsf(dy - r1); s += (d <= 1.f / 9.f) ? 4.5f * d * d : d - 0.5f / 9.f;
                d = fabsf(dw - r2); s += (d <= 1.f / 9.f) ? 4.5f * d * d : d - 0.5f / 9.f;
                d = fabsf(dh - r3); s += (d <= 1.f / 9.f) ? 4.5f * d * d : d - 0.5f / 9.f;
                atomicAdd(&s_reg[b], s);
            }
        }
    }
    __syncthreads();
    if (tid < B) {
        if (s_npos[tid]) atomicAdd(&g_npos[tid], s_npos[tid]);
        if (s_reg[tid] != 0.f) atomicAdd(&g_reg[tid], s_reg[tid]);
    }
}

// Kernel 2: classification consistency. One thread per (a,c) element,
// batch loop inside: each of the 62.8 MB read exactly once, coalesced.
__global__ void __launch_bounds__(256) k_cls(
    const float* __restrict__ cls_in,   // [B,A,C]
    const float* __restrict__ ema_in)   // [B,A,C]
{
    __shared__ float s_acc[B];
    int tid = threadIdx.x;
    if (tid < B) s_acc[tid] = 0.f;
    __syncthreads();

    float acc[B];
    #pragma unroll
    for (int b = 0; b < B; b++) acc[b] = 0.f;

    int base = blockIdx.x * (256 * 4) + tid;
    #pragma unroll
    for (int j = 0; j < 4; j++) {
        int idx = base + j * 256;
        if (idx < AC) {
            int a = idx / C;
            float e[B];
            float S = 0.f;
            #pragma unroll
            for (int b = 0; b < B; b++) {
                e[b] = ema_in[(size_t)b * AC + idx];  // unclamped for alpha (bug-faithful)
                S += e[b];
            }
            float alpha = 0.4f + 0.9f * S;  // B*a0 + (a1-a0)*S
            #pragma unroll
            for (int b = 0; b < B; b++) {
                if (g_assigned[b][a]) {
                    float ec = fminf(fmaxf(e[b], 1e-4f), 1.f - 1e-4f);
                    float c  = fminf(fmaxf(cls_in[(size_t)b * AC + idx], 1e-4f), 1.f - 1e-4f);
                    float bce = -(ec * __logf(c) + (1.f - ec) * __logf(1.f - c));
                    float d = ec - c;
                    acc[b] += alpha * (d * d) * bce;
                }
            }
        }
    }

    // hierarchical reduction: warp shuffle -> shared -> global atomics
    #pragma unroll
    for (int b = 0; b < B; b++) {
        float v = acc[b];
        #pragma unroll
        for (int o = 16; o; o >>= 1) v += __shfl_down_sync(0xffffffffu, v, o);
        if ((tid & 31) == 0) atomicAdd(&s_acc[b], v);
    }
    __syncthreads();
    if (tid < B) atomicAdd(&g_cls[tid], s_acc[tid]);
}

__global__ void k_final(float* __restrict__ out) {
    float cs = 0.f, rs = 0.f;
    #pragma unroll
    for (int b = 0; b < B; b++) {
        float np = (float)g_npos[b];
        float mx = fmaxf(np, 1.f);
        cs += g_cls[b] / mx;
        rs += (np > 0.f) ? g_reg[b] / (4.f * mx) : 0.f;
    }
    out[0] = cs * (1.f / (float)B);
    out[1] = rs * (1.f / (float)B);
}

extern "C" void kernel_launch(void* const* d_in, const int* in_sizes, int n_in,
                              void* d_out, int out_size) {
    const float* classifications     = (const float*)d_in[0];
    const float* regressions         = (const float*)d_in[1];
    const float* anchors             = (const float*)d_in[2];
    const float* ema_classifications = (const float*)d_in[3];
    const float* ema_classes         = (const float*)d_in[4];
    const float* ema_bboxes          = (const float*)d_in[5];
    const int*   ema_counts          = (const int*)d_in[6];
    const float* annotations         = (const float*)d_in[7];
    float* out = (float*)d_out;

    k_init<<<1, 32>>>();
    k_assign<<<(A + 255) / 256, 256>>>(regressions, anchors, ema_classes,
                                       ema_bboxes, ema_counts, annotations);
    k_cls<<<(AC + 1023) / 1024, 256>>>(classifications, ema_classifications);
    k_final<<<1, 1>>>(out);
}